// round 1
// baseline (speedup 1.0000x reference)
#include <cuda_runtime.h>
#include <cuda_bf16.h>
#include <math.h>

// Problem constants
#define B_  4
#define L_  1024
#define D_  1024
#define DF_ 4096
#define E_  32768
#define R_  64
#define M_  (B_ * L_)          // 4096 rows total
#define EPS_ 1e-6f

// ---------------------------------------------------------------------------
// Scratch (static __device__ globals; allocation-free per harness rules)
// ---------------------------------------------------------------------------
__device__ float g_hsnorm[M_ * D_];     // ln0(hidden)
__device__ float g_q[M_ * D_];
__device__ float g_k[M_ * D_];
__device__ float g_v[M_ * D_];
__device__ float g_o[M_ * D_];          // attention output o = wv/z
__device__ float g_t1[M_ * D_];         // x + o@Wo + bo (pre-ln1)
__device__ float g_out[M_ * D_];        // post-ln1
__device__ float g_h1[M_ * DF_];        // relu(out@W1 + b1)
__device__ float g_f[M_ * D_];          // out + ffn (pre-ln2)
__device__ float g_score[B_ * E_];
__device__ int   g_perm[B_ * E_];       // edge ids sorted (stable) by dst, per batch
__device__ int   g_cnt[B_ * L_];
__device__ int   g_off[B_ * (L_ + 1)];

// ---------------------------------------------------------------------------
// LayerNorm: one block (256 threads) per row of 1024 floats
// ---------------------------------------------------------------------------
__device__ __forceinline__ void row_moments(float4 v, float& mean, float& rstd,
                                            float* sh1, float* sh2) {
    float s  = v.x + v.y + v.z + v.w;
    float sq = v.x * v.x + v.y * v.y + v.z * v.z + v.w * v.w;
    #pragma unroll
    for (int o = 16; o; o >>= 1) {
        s  += __shfl_xor_sync(0xffffffffu, s, o);
        sq += __shfl_xor_sync(0xffffffffu, sq, o);
    }
    int warp = threadIdx.x >> 5, lane = threadIdx.x & 31;
    if (lane == 0) { sh1[warp] = s; sh2[warp] = sq; }
    __syncthreads();
    if (threadIdx.x < 8) {
        s = sh1[threadIdx.x]; sq = sh2[threadIdx.x];
        #pragma unroll
        for (int o = 4; o; o >>= 1) {
            s  += __shfl_xor_sync(0xffu, s, o);
            sq += __shfl_xor_sync(0xffu, sq, o);
        }
        if (threadIdx.x == 0) { sh1[0] = s; sh2[0] = sq; }
    }
    __syncthreads();
    mean = sh1[0] * (1.0f / D_);
    float var = sh2[0] * (1.0f / D_) - mean * mean;
    rstd = rsqrtf(var + EPS_);
}

__global__ void ln_kernel(const float* __restrict__ x, const float* __restrict__ g,
                          const float* __restrict__ b, float* __restrict__ y) {
    __shared__ float sh1[8], sh2[8];
    size_t row = blockIdx.x;
    int t = threadIdx.x;
    float4 v = ((const float4*)(x + row * D_))[t];
    float mean, rstd;
    row_moments(v, mean, rstd, sh1, sh2);
    float4 gv = ((const float4*)g)[t];
    float4 bv = ((const float4*)b)[t];
    float4 o;
    o.x = (v.x - mean) * rstd * gv.x + bv.x;
    o.y = (v.y - mean) * rstd * gv.y + bv.y;
    o.z = (v.z - mean) * rstd * gv.z + bv.z;
    o.w = (v.w - mean) * rstd * gv.w + bv.w;
    ((float4*)(y + row * D_))[t] = o;
}

// Final: out = hidden + elu(layer_norm(f))
__global__ void ln_elu_res_kernel(const float* __restrict__ x, const float* __restrict__ g,
                                  const float* __restrict__ b,
                                  const float* __restrict__ hidden,
                                  float* __restrict__ out) {
    __shared__ float sh1[8], sh2[8];
    size_t row = blockIdx.x;
    int t = threadIdx.x;
    float4 v = ((const float4*)(x + row * D_))[t];
    float mean, rstd;
    row_moments(v, mean, rstd, sh1, sh2);
    float4 gv = ((const float4*)g)[t];
    float4 bv = ((const float4*)b)[t];
    float4 hv = ((const float4*)(hidden + row * D_))[t];
    float n0 = (v.x - mean) * rstd * gv.x + bv.x;
    float n1 = (v.y - mean) * rstd * gv.y + bv.y;
    float n2 = (v.z - mean) * rstd * gv.z + bv.z;
    float n3 = (v.w - mean) * rstd * gv.w + bv.w;
    float4 o;
    o.x = hv.x + (n0 > 0.f ? n0 : expm1f(n0));
    o.y = hv.y + (n1 > 0.f ? n1 : expm1f(n1));
    o.z = hv.z + (n2 > 0.f ? n2 : expm1f(n2));
    o.w = hv.w + (n3 > 0.f ? n3 : expm1f(n3));
    ((float4*)(out + row * D_))[t] = o;
}

// ---------------------------------------------------------------------------
// SGEMM: C[M,N] = A[M,K] @ B[K,N] (+bias) (+res) (+relu); 128x128 tiles, BK=8
// 256 threads, 8x8 micro-tile per thread.
// ---------------------------------------------------------------------------
template <bool RELU, bool BIAS, bool RES>
__global__ __launch_bounds__(256) void sgemm_kernel(
    const float* __restrict__ A, const float* __restrict__ Bm,
    const float* __restrict__ bias, const float* __restrict__ res,
    float* __restrict__ C, int M, int N, int K) {
    __shared__ float As[8][128];
    __shared__ float Bs[8][128];
    int tid = threadIdx.x;
    int tx = tid & 15, ty = tid >> 4;
    int bn = blockIdx.x * 128, bm = blockIdx.y * 128;
    const float* Ab = A + (size_t)bm * K;
    const float* Bb = Bm + bn;
    int arow = tid >> 1, acol = (tid & 1) * 4;
    int brow = tid >> 5, bcol = (tid & 31) * 4;

    float acc[8][8];
    #pragma unroll
    for (int i = 0; i < 8; i++)
        #pragma unroll
        for (int j = 0; j < 8; j++) acc[i][j] = 0.f;

    for (int k0 = 0; k0 < K; k0 += 8) {
        float4 av = *(const float4*)(Ab + (size_t)arow * K + (k0 + acol));
        float4 bv = *(const float4*)(Bb + (size_t)(k0 + brow) * N + bcol);
        As[acol + 0][arow] = av.x;
        As[acol + 1][arow] = av.y;
        As[acol + 2][arow] = av.z;
        As[acol + 3][arow] = av.w;
        *(float4*)(&Bs[brow][bcol]) = bv;
        __syncthreads();
        #pragma unroll
        for (int kk = 0; kk < 8; kk++) {
            float a[8], bf[8];
            #pragma unroll
            for (int i = 0; i < 8; i++) a[i] = As[kk][ty * 8 + i];
            #pragma unroll
            for (int j = 0; j < 8; j++) bf[j] = Bs[kk][tx * 8 + j];
            #pragma unroll
            for (int i = 0; i < 8; i++)
                #pragma unroll
                for (int j = 0; j < 8; j++)
                    acc[i][j] = fmaf(a[i], bf[j], acc[i][j]);
        }
        __syncthreads();
    }

    #pragma unroll
    for (int i = 0; i < 8; i++) {
        int row = bm + ty * 8 + i;
        #pragma unroll
        for (int j = 0; j < 8; j += 4) {
            int col = bn + tx * 8 + j;
            float4 v = make_float4(acc[i][j], acc[i][j + 1], acc[i][j + 2], acc[i][j + 3]);
            if (BIAS) {
                float4 bb = *(const float4*)(bias + col);
                v.x += bb.x; v.y += bb.y; v.z += bb.z; v.w += bb.w;
            }
            if (RES) {
                float4 rr = *(const float4*)(res + (size_t)row * N + col);
                v.x += rr.x; v.y += rr.y; v.z += rr.z; v.w += rr.w;
            }
            if (RELU) {
                v.x = fmaxf(v.x, 0.f); v.y = fmaxf(v.y, 0.f);
                v.z = fmaxf(v.z, 0.f); v.w = fmaxf(v.w, 0.f);
            }
            *(float4*)(C + (size_t)row * N + col) = v;
        }
    }
}

// ---------------------------------------------------------------------------
// Edge scores: one warp per edge. score = exp(clip(dot(k[src]+e, q[dst])/32))
// ---------------------------------------------------------------------------
__global__ void score_kernel(const float* __restrict__ Q, const float* __restrict__ Km,
                             const float* __restrict__ rel_table,
                             const int* __restrict__ src, const int* __restrict__ dst,
                             const int* __restrict__ rel, float* __restrict__ score) {
    int idx = blockIdx.x * 4 + threadIdx.y;   // 0 .. B*E-1
    int b = idx >> 15;                        // / E_
    int lane = threadIdx.x;
    int s = src[idx], d = dst[idx], r = rel[idx];
    const float4* kr = (const float4*)(Km + ((size_t)b * L_ + s) * D_);
    const float4* qr = (const float4*)(Q + ((size_t)b * L_ + d) * D_);
    const float4* er = (const float4*)(rel_table + (size_t)r * D_);
    float acc = 0.f;
    #pragma unroll
    for (int i = 0; i < 8; i++) {
        int c = lane + 32 * i;
        float4 kv = kr[c], qv = qr[c], ev = er[c];
        acc = fmaf(kv.x + ev.x, qv.x, acc);
        acc = fmaf(kv.y + ev.y, qv.y, acc);
        acc = fmaf(kv.z + ev.z, qv.z, acc);
        acc = fmaf(kv.w + ev.w, qv.w, acc);
    }
    #pragma unroll
    for (int o = 16; o; o >>= 1) acc += __shfl_xor_sync(0xffffffffu, acc, o);
    if (lane == 0) {
        float sc = acc * 0.03125f;            // / sqrt(1024) = /32
        sc = fminf(fmaxf(sc, -10.f), 10.f);
        score[idx] = expf(sc);
    }
}

// ---------------------------------------------------------------------------
// Deterministic binning: histogram -> exclusive scan -> stable fill
// ---------------------------------------------------------------------------
__global__ void zero_cnt_kernel() {
    int i = blockIdx.x * 256 + threadIdx.x;
    if (i < B_ * L_) g_cnt[i] = 0;
}

__global__ void hist_kernel(const int* __restrict__ edge_dst) {
    int idx = blockIdx.x * 256 + threadIdx.x;
    if (idx < B_ * E_) atomicAdd(&g_cnt[(idx >> 15) * L_ + edge_dst[idx]], 1);
}

__global__ void scan_kernel() {
    int b = blockIdx.x, t = threadIdx.x;
    __shared__ int s[L_];
    int c = g_cnt[b * L_ + t];
    s[t] = c;
    __syncthreads();
    for (int off = 1; off < L_; off <<= 1) {
        int v = (t >= off) ? s[t - off] : 0;
        __syncthreads();
        s[t] += v;
        __syncthreads();
    }
    g_off[b * (L_ + 1) + t] = s[t] - c;       // exclusive prefix
    if (t == L_ - 1) g_off[b * (L_ + 1) + L_] = s[t];
}

// Each thread owns one (batch, dst) and scans the whole edge list in order:
// bin contents are stably ordered by edge id -> deterministic fp accumulation.
__global__ void fill_kernel(const int* __restrict__ edge_dst) {
    int gid = blockIdx.x * blockDim.x + threadIdx.x;
    if (gid >= B_ * L_) return;
    int b = gid >> 10, node = gid & (L_ - 1);
    const int4* dv = (const int4*)(edge_dst + b * E_);
    int w = g_off[b * (L_ + 1) + node];
    int* pb = g_perm + b * E_;
    #pragma unroll 4
    for (int i = 0; i < E_ / 4; i++) {
        int4 d = dv[i];
        int e = 4 * i;
        if (d.x == node) pb[w++] = e;
        if (d.y == node) pb[w++] = e + 1;
        if (d.z == node) pb[w++] = e + 2;
        if (d.w == node) pb[w++] = e + 3;
    }
}

// ---------------------------------------------------------------------------
// Aggregation: block per (dst,b). Thread t owns columns [4t,4t+4).
// o[dst] = (sum_e score_e * (v[src_e] + rel_e)) / (sum_e score_e)
// ---------------------------------------------------------------------------
__global__ void agg_kernel(const float* __restrict__ V, const float* __restrict__ rel_table,
                           const int* __restrict__ src, const int* __restrict__ rel,
                           const float* __restrict__ score) {
    int node = blockIdx.x, b = blockIdx.y;
    int t = threadIdx.x;
    int beg = g_off[b * (L_ + 1) + node];
    int end = g_off[b * (L_ + 1) + node + 1];
    const int* pb = g_perm + b * E_;
    float4 acc = make_float4(0.f, 0.f, 0.f, 0.f);
    float z = 0.f;
    for (int i = beg; i < end; i++) {
        int e = pb[i];
        float s = score[b * E_ + e];
        int sn = src[b * E_ + e];
        int r = rel[b * E_ + e];
        float4 vv = *(const float4*)(V + ((size_t)b * L_ + sn) * D_ + 4 * t);
        float4 ev = *(const float4*)(rel_table + (size_t)r * D_ + 4 * t);
        acc.x = fmaf(s, vv.x + ev.x, acc.x);
        acc.y = fmaf(s, vv.y + ev.y, acc.y);
        acc.z = fmaf(s, vv.z + ev.z, acc.z);
        acc.w = fmaf(s, vv.w + ev.w, acc.w);
        z += s;
    }
    float inv = 1.0f / z;
    float4 o = make_float4(acc.x * inv, acc.y * inv, acc.z * inv, acc.w * inv);
    *(float4*)(g_o + ((size_t)b * L_ + node) * D_ + 4 * t) = o;
}

// ---------------------------------------------------------------------------
// Launch
// ---------------------------------------------------------------------------
extern "C" void kernel_launch(void* const* d_in, const int* in_sizes, int n_in,
                              void* d_out, int out_size) {
    const float* hidden  = (const float*)d_in[0];
    const float* rel_tab = (const float*)d_in[1];
    const float* Wq = (const float*)d_in[2];
    const float* bq = (const float*)d_in[3];
    const float* Wk = (const float*)d_in[4];
    const float* Wv = (const float*)d_in[5];
    const float* Wo = (const float*)d_in[6];
    const float* bo = (const float*)d_in[7];
    const float* ln0g = (const float*)d_in[8];
    const float* ln0b = (const float*)d_in[9];
    const float* ln1g = (const float*)d_in[10];
    const float* ln1b = (const float*)d_in[11];
    const float* W1 = (const float*)d_in[12];
    const float* b1 = (const float*)d_in[13];
    const float* W2 = (const float*)d_in[14];
    const float* b2 = (const float*)d_in[15];
    const float* ln2g = (const float*)d_in[16];
    const float* ln2b = (const float*)d_in[17];
    const int* esrc = (const int*)d_in[18];
    const int* edst = (const int*)d_in[19];
    const int* erel = (const int*)d_in[20];
    float* out = (float*)d_out;

    float *p_hsnorm, *p_q, *p_k, *p_v, *p_o, *p_t1, *p_out, *p_h1, *p_f, *p_score;
    cudaGetSymbolAddress((void**)&p_hsnorm, g_hsnorm);
    cudaGetSymbolAddress((void**)&p_q, g_q);
    cudaGetSymbolAddress((void**)&p_k, g_k);
    cudaGetSymbolAddress((void**)&p_v, g_v);
    cudaGetSymbolAddress((void**)&p_o, g_o);
    cudaGetSymbolAddress((void**)&p_t1, g_t1);
    cudaGetSymbolAddress((void**)&p_out, g_out);
    cudaGetSymbolAddress((void**)&p_h1, g_h1);
    cudaGetSymbolAddress((void**)&p_f, g_f);
    cudaGetSymbolAddress((void**)&p_score, g_score);

    // 1. ln0
    ln_kernel<<<M_, 256>>>(hidden, ln0g, ln0b, p_hsnorm);

    // 2. Q, K, V GEMMs  (M=4096, N=1024, K=1024)
    dim3 gD(D_ / 128, M_ / 128);
    sgemm_kernel<false, true,  false><<<gD, 256>>>(p_hsnorm, Wq, bq, nullptr, p_q, M_, D_, D_);
    sgemm_kernel<false, false, false><<<gD, 256>>>(p_hsnorm, Wk, nullptr, nullptr, p_k, M_, D_, D_);
    sgemm_kernel<false, false, false><<<gD, 256>>>(p_hsnorm, Wv, nullptr, nullptr, p_v, M_, D_, D_);

    // 3. edge scores
    score_kernel<<<(B_ * E_) / 4, dim3(32, 4)>>>(p_q, p_k, rel_tab, esrc, edst, erel, p_score);

    // 4. deterministic binning by dst
    zero_cnt_kernel<<<(B_ * L_) / 256, 256>>>();
    hist_kernel<<<(B_ * E_) / 256, 256>>>(edst);
    scan_kernel<<<B_, L_>>>();
    fill_kernel<<<128, 32>>>(edst);

    // 5. aggregation -> g_o
    agg_kernel<<<dim3(L_, B_), 256>>>(p_v, rel_tab, esrc, erel, p_score);

    // 6. t1 = hs_norm + o @ Wo + bo ; ln1 -> out
    sgemm_kernel<false, true, true><<<gD, 256>>>(p_o, Wo, bo, p_hsnorm, p_t1, M_, D_, D_);
    ln_kernel<<<M_, 256>>>(p_t1, ln1g, ln1b, p_out);

    // 7. FFN: h1 = relu(out @ W1 + b1); f = out + h1 @ W2 + b2
    dim3 gDF(DF_ / 128, M_ / 128);
    sgemm_kernel<true, true, false><<<gDF, 256>>>(p_out, W1, b1, nullptr, p_h1, M_, DF_, D_);
    sgemm_kernel<false, true, true><<<gD, 256>>>(p_h1, W2, b2, p_out, p_f, M_, D_, DF_);

    // 8. graph_rep = ln2(f); out = hidden + elu(graph_rep)
    ln_elu_res_kernel<<<M_, 256>>>(p_f, ln2g, ln2b, hidden, out);
}

// round 2
// speedup vs baseline: 1.9455x; 1.9455x over previous
#include <cuda_runtime.h>
#include <cuda_bf16.h>
#include <math.h>

// Problem constants
#define B_  4
#define L_  1024
#define D_  1024
#define DF_ 4096
#define E_  32768
#define R_  64
#define M_  (B_ * L_)          // 4096 rows total
#define EPS_ 1e-6f

// ---------------------------------------------------------------------------
// Scratch (static __device__ globals; allocation-free per harness rules)
// ---------------------------------------------------------------------------
__device__ float g_hsnorm[M_ * D_];     // ln0(hidden)
__device__ float g_q[M_ * D_];
__device__ float g_k[M_ * D_];
__device__ float g_v[M_ * D_];
__device__ float g_o[M_ * D_];          // attention output o = wv/z
__device__ float g_t1[M_ * D_];         // x + o@Wo + bo (pre-ln1)
__device__ float g_out[M_ * D_];        // post-ln1
__device__ float g_h1[M_ * DF_];        // relu(out@W1 + b1)
__device__ float g_f[M_ * D_];          // out + ffn (pre-ln2)
__device__ float g_score[B_ * E_];
__device__ int   g_perm[B_ * E_];       // edge ids stably binned by dst, per batch
__device__ int   g_cnt[B_ * L_];
__device__ int   g_off[B_ * (L_ + 1)];

// ---------------------------------------------------------------------------
// LayerNorm helpers
// ---------------------------------------------------------------------------
__device__ __forceinline__ void row_moments(float4 v, float& mean, float& rstd,
                                            float* sh1, float* sh2) {
    float s  = v.x + v.y + v.z + v.w;
    float sq = v.x * v.x + v.y * v.y + v.z * v.z + v.w * v.w;
    #pragma unroll
    for (int o = 16; o; o >>= 1) {
        s  += __shfl_xor_sync(0xffffffffu, s, o);
        sq += __shfl_xor_sync(0xffffffffu, sq, o);
    }
    int warp = threadIdx.x >> 5, lane = threadIdx.x & 31;
    if (lane == 0) { sh1[warp] = s; sh2[warp] = sq; }
    __syncthreads();
    if (threadIdx.x < 8) {
        s = sh1[threadIdx.x]; sq = sh2[threadIdx.x];
        #pragma unroll
        for (int o = 4; o; o >>= 1) {
            s  += __shfl_xor_sync(0xffu, s, o);
            sq += __shfl_xor_sync(0xffu, sq, o);
        }
        if (threadIdx.x == 0) { sh1[0] = s; sh2[0] = sq; }
    }
    __syncthreads();
    mean = sh1[0] * (1.0f / D_);
    float var = sh2[0] * (1.0f / D_) - mean * mean;
    rstd = rsqrtf(var + EPS_);
}

__global__ void ln_kernel(const float* __restrict__ x, const float* __restrict__ g,
                          const float* __restrict__ b, float* __restrict__ y) {
    __shared__ float sh1[8], sh2[8];
    size_t row = blockIdx.x;
    int t = threadIdx.x;
    float4 v = ((const float4*)(x + row * D_))[t];
    float mean, rstd;
    row_moments(v, mean, rstd, sh1, sh2);
    float4 gv = ((const float4*)g)[t];
    float4 bv = ((const float4*)b)[t];
    float4 o;
    o.x = (v.x - mean) * rstd * gv.x + bv.x;
    o.y = (v.y - mean) * rstd * gv.y + bv.y;
    o.z = (v.z - mean) * rstd * gv.z + bv.z;
    o.w = (v.w - mean) * rstd * gv.w + bv.w;
    ((float4*)(y + row * D_))[t] = o;
}

__global__ void ln_elu_res_kernel(const float* __restrict__ x, const float* __restrict__ g,
                                  const float* __restrict__ b,
                                  const float* __restrict__ hidden,
                                  float* __restrict__ out) {
    __shared__ float sh1[8], sh2[8];
    size_t row = blockIdx.x;
    int t = threadIdx.x;
    float4 v = ((const float4*)(x + row * D_))[t];
    float mean, rstd;
    row_moments(v, mean, rstd, sh1, sh2);
    float4 gv = ((const float4*)g)[t];
    float4 bv = ((const float4*)b)[t];
    float4 hv = ((const float4*)(hidden + row * D_))[t];
    float n0 = (v.x - mean) * rstd * gv.x + bv.x;
    float n1 = (v.y - mean) * rstd * gv.y + bv.y;
    float n2 = (v.z - mean) * rstd * gv.z + bv.z;
    float n3 = (v.w - mean) * rstd * gv.w + bv.w;
    float4 o;
    o.x = hv.x + (n0 > 0.f ? n0 : expm1f(n0));
    o.y = hv.y + (n1 > 0.f ? n1 : expm1f(n1));
    o.z = hv.z + (n2 > 0.f ? n2 : expm1f(n2));
    o.w = hv.w + (n3 > 0.f ? n3 : expm1f(n3));
    ((float4*)(out + row * D_))[t] = o;
}

// ---------------------------------------------------------------------------
// TF32 tensor-core GEMM: C[M,N] = A[M,K] @ B[K,N] (+bias)(+res)(+relu)
// 128x128 block tile, 8 warps (2x4), 64x32 warp tile, BK=16, m16n8k8 mma.
// SMEM k-major with pad 136 -> conflict-free fragment LDS.
// ---------------------------------------------------------------------------
__device__ __forceinline__ unsigned f2tf(float x) {
    unsigned r;
    asm("cvt.rna.tf32.f32 %0, %1;" : "=r"(r) : "f"(x));
    return r;
}

__device__ __forceinline__ void mma_tf32(float* c, const unsigned* a, const unsigned* b) {
    asm volatile(
        "mma.sync.aligned.m16n8k8.row.col.f32.tf32.tf32.f32 "
        "{%0,%1,%2,%3}, {%4,%5,%6,%7}, {%8,%9}, {%0,%1,%2,%3};"
        : "+f"(c[0]), "+f"(c[1]), "+f"(c[2]), "+f"(c[3])
        : "r"(a[0]), "r"(a[1]), "r"(a[2]), "r"(a[3]), "r"(b[0]), "r"(b[1]));
}

#define SW 136   // smem row pitch (words); 8-bank shift per k-row -> conflict-free

template <bool RELU, bool BIAS, bool RES>
__global__ __launch_bounds__(256, 2) void mma_gemm_kernel(
    const float* __restrict__ A, const float* __restrict__ Bm,
    const float* __restrict__ bias, const float* __restrict__ res,
    float* __restrict__ C, int M, int N, int K) {
    __shared__ unsigned As[16][SW];   // As[k][m]
    __shared__ unsigned Bs[16][SW];   // Bs[k][n]
    int tid = threadIdx.x;
    int warp = tid >> 5, lane = tid & 31;
    int wm = (warp & 1) * 64;
    int wn = (warp >> 1) * 32;
    int g = lane >> 2, tg = lane & 3;
    int bm = blockIdx.y * 128, bn = blockIdx.x * 128;

    float acc[4][4][4];
    #pragma unroll
    for (int i = 0; i < 4; i++)
        #pragma unroll
        for (int j = 0; j < 4; j++)
            #pragma unroll
            for (int r = 0; r < 4; r++) acc[i][j][r] = 0.f;

    int arow = tid >> 1;            // 0..127
    int akc  = (tid & 1) * 8;       // 0 or 8
    int brow = tid >> 4;            // 0..15
    int bcol = (tid & 15) * 8;      // 0..120

    const float* Aptr = A + (size_t)(bm + arow) * K + akc;
    const float* Bptr = Bm + (size_t)brow * N + bn + bcol;

    for (int k0 = 0; k0 < K; k0 += 16) {
        float4 a0 = *(const float4*)(Aptr);
        float4 a1 = *(const float4*)(Aptr + 4);
        Aptr += 16;
        float4 b0 = *(const float4*)(Bptr);
        float4 b1 = *(const float4*)(Bptr + 4);
        Bptr += (size_t)16 * N;

        __syncthreads();   // previous iter's compute done before overwrite
        // A transposed store (k-major)
        As[akc + 0][arow] = f2tf(a0.x);
        As[akc + 1][arow] = f2tf(a0.y);
        As[akc + 2][arow] = f2tf(a0.z);
        As[akc + 3][arow] = f2tf(a0.w);
        As[akc + 4][arow] = f2tf(a1.x);
        As[akc + 5][arow] = f2tf(a1.y);
        As[akc + 6][arow] = f2tf(a1.z);
        As[akc + 7][arow] = f2tf(a1.w);
        // B direct (k-major already)
        uint4 bb0 = make_uint4(f2tf(b0.x), f2tf(b0.y), f2tf(b0.z), f2tf(b0.w));
        uint4 bb1 = make_uint4(f2tf(b1.x), f2tf(b1.y), f2tf(b1.z), f2tf(b1.w));
        *(uint4*)(&Bs[brow][bcol])     = bb0;
        *(uint4*)(&Bs[brow][bcol + 4]) = bb1;
        __syncthreads();

        #pragma unroll
        for (int ks = 0; ks < 2; ks++) {
            unsigned af[4][4];
            #pragma unroll
            for (int mt = 0; mt < 4; mt++) {
                int r = wm + mt * 16 + g;
                af[mt][0] = As[ks * 8 + tg][r];
                af[mt][1] = As[ks * 8 + tg][r + 8];
                af[mt][2] = As[ks * 8 + tg + 4][r];
                af[mt][3] = As[ks * 8 + tg + 4][r + 8];
            }
            unsigned bf[4][2];
            #pragma unroll
            for (int nt = 0; nt < 4; nt++) {
                int cc = wn + nt * 8 + g;
                bf[nt][0] = Bs[ks * 8 + tg][cc];
                bf[nt][1] = Bs[ks * 8 + tg + 4][cc];
            }
            #pragma unroll
            for (int mt = 0; mt < 4; mt++)
                #pragma unroll
                for (int nt = 0; nt < 4; nt++)
                    mma_tf32(acc[mt][nt], af[mt], bf[nt]);
        }
    }

    // Epilogue
    #pragma unroll
    for (int mt = 0; mt < 4; mt++) {
        #pragma unroll
        for (int nt = 0; nt < 4; nt++) {
            int col = bn + wn + nt * 8 + tg * 2;
            #pragma unroll
            for (int h = 0; h < 2; h++) {
                int row = bm + wm + mt * 16 + g + h * 8;
                float vx = acc[mt][nt][2 * h];
                float vy = acc[mt][nt][2 * h + 1];
                if (BIAS) {
                    float2 bb = *(const float2*)(bias + col);
                    vx += bb.x; vy += bb.y;
                }
                if (RES) {
                    float2 rr = *(const float2*)(res + (size_t)row * N + col);
                    vx += rr.x; vy += rr.y;
                }
                if (RELU) { vx = fmaxf(vx, 0.f); vy = fmaxf(vy, 0.f); }
                *(float2*)(C + (size_t)row * N + col) = make_float2(vx, vy);
            }
        }
    }
}

// ---------------------------------------------------------------------------
// Edge scores: one warp per edge. score = exp(clip(dot(k[src]+e, q[dst])/32))
// ---------------------------------------------------------------------------
__global__ void score_kernel(const float* __restrict__ Q, const float* __restrict__ Km,
                             const float* __restrict__ rel_table,
                             const int* __restrict__ src, const int* __restrict__ dst,
                             const int* __restrict__ rel, float* __restrict__ score) {
    int idx = blockIdx.x * 4 + threadIdx.y;   // 0 .. B*E-1
    int b = idx >> 15;                        // / E_
    int lane = threadIdx.x;
    int s = src[idx], d = dst[idx], r = rel[idx];
    const float4* kr = (const float4*)(Km + ((size_t)b * L_ + s) * D_);
    const float4* qr = (const float4*)(Q + ((size_t)b * L_ + d) * D_);
    const float4* er = (const float4*)(rel_table + (size_t)r * D_);
    float acc = 0.f;
    #pragma unroll
    for (int i = 0; i < 8; i++) {
        int c = lane + 32 * i;
        float4 kv = kr[c], qv = qr[c], ev = er[c];
        acc = fmaf(kv.x + ev.x, qv.x, acc);
        acc = fmaf(kv.y + ev.y, qv.y, acc);
        acc = fmaf(kv.z + ev.z, qv.z, acc);
        acc = fmaf(kv.w + ev.w, qv.w, acc);
    }
    #pragma unroll
    for (int o = 16; o; o >>= 1) acc += __shfl_xor_sync(0xffffffffu, acc, o);
    if (lane == 0) {
        float sc = acc * 0.03125f;            // / sqrt(1024) = /32
        sc = fminf(fmaxf(sc, -10.f), 10.f);
        score[idx] = expf(sc);
    }
}

// ---------------------------------------------------------------------------
// Deterministic binning: histogram -> exclusive scan -> stable fill
// ---------------------------------------------------------------------------
__global__ void zero_cnt_kernel() {
    int i = blockIdx.x * 256 + threadIdx.x;
    if (i < B_ * L_) g_cnt[i] = 0;
}

__global__ void hist_kernel(const int* __restrict__ edge_dst) {
    int idx = blockIdx.x * 256 + threadIdx.x;
    if (idx < B_ * E_) atomicAdd(&g_cnt[(idx >> 15) * L_ + edge_dst[idx]], 1);
}

__global__ void scan_kernel() {
    int b = blockIdx.x, t = threadIdx.x;
    __shared__ int s[L_];
    int c = g_cnt[b * L_ + t];
    s[t] = c;
    __syncthreads();
    for (int off = 1; off < L_; off <<= 1) {
        int v = (t >= off) ? s[t - off] : 0;
        __syncthreads();
        s[t] += v;
        __syncthreads();
    }
    g_off[b * (L_ + 1) + t] = s[t] - c;       // exclusive prefix
    if (t == L_ - 1) g_off[b * (L_ + 1) + L_] = s[t];
}

__global__ void fill_kernel(const int* __restrict__ edge_dst) {
    int gid = blockIdx.x * blockDim.x + threadIdx.x;
    if (gid >= B_ * L_) return;
    int b = gid >> 10, node = gid & (L_ - 1);
    const int4* dv = (const int4*)(edge_dst + b * E_);
    int w = g_off[b * (L_ + 1) + node];
    int* pb = g_perm + b * E_;
    #pragma unroll 4
    for (int i = 0; i < E_ / 4; i++) {
        int4 d = dv[i];
        int e = 4 * i;
        if (d.x == node) pb[w++] = e;
        if (d.y == node) pb[w++] = e + 1;
        if (d.z == node) pb[w++] = e + 2;
        if (d.w == node) pb[w++] = e + 3;
    }
}

// ---------------------------------------------------------------------------
// Aggregation: block per (dst,b). Thread t owns columns [4t,4t+4).
// ---------------------------------------------------------------------------
__global__ void agg_kernel(const float* __restrict__ V, const float* __restrict__ rel_table,
                           const int* __restrict__ src, const int* __restrict__ rel,
                           const float* __restrict__ score) {
    int node = blockIdx.x, b = blockIdx.y;
    int t = threadIdx.x;
    int beg = g_off[b * (L_ + 1) + node];
    int end = g_off[b * (L_ + 1) + node + 1];
    const int* pb = g_perm + b * E_;
    float4 acc = make_float4(0.f, 0.f, 0.f, 0.f);
    float z = 0.f;
    for (int i = beg; i < end; i++) {
        int e = pb[i];
        float s = score[b * E_ + e];
        int sn = src[b * E_ + e];
        int r = rel[b * E_ + e];
        float4 vv = *(const float4*)(V + ((size_t)b * L_ + sn) * D_ + 4 * t);
        float4 ev = *(const float4*)(rel_table + (size_t)r * D_ + 4 * t);
        acc.x = fmaf(s, vv.x + ev.x, acc.x);
        acc.y = fmaf(s, vv.y + ev.y, acc.y);
        acc.z = fmaf(s, vv.z + ev.z, acc.z);
        acc.w = fmaf(s, vv.w + ev.w, acc.w);
        z += s;
    }
    float inv = 1.0f / z;
    float4 o = make_float4(acc.x * inv, acc.y * inv, acc.z * inv, acc.w * inv);
    *(float4*)(g_o + ((size_t)b * L_ + node) * D_ + 4 * t) = o;
}

// ---------------------------------------------------------------------------
// Launch
// ---------------------------------------------------------------------------
extern "C" void kernel_launch(void* const* d_in, const int* in_sizes, int n_in,
                              void* d_out, int out_size) {
    const float* hidden  = (const float*)d_in[0];
    const float* rel_tab = (const float*)d_in[1];
    const float* Wq = (const float*)d_in[2];
    const float* bq = (const float*)d_in[3];
    const float* Wk = (const float*)d_in[4];
    const float* Wv = (const float*)d_in[5];
    const float* Wo = (const float*)d_in[6];
    const float* bo = (const float*)d_in[7];
    const float* ln0g = (const float*)d_in[8];
    const float* ln0b = (const float*)d_in[9];
    const float* ln1g = (const float*)d_in[10];
    const float* ln1b = (const float*)d_in[11];
    const float* W1 = (const float*)d_in[12];
    const float* b1 = (const float*)d_in[13];
    const float* W2 = (const float*)d_in[14];
    const float* b2 = (const float*)d_in[15];
    const float* ln2g = (const float*)d_in[16];
    const float* ln2b = (const float*)d_in[17];
    const int* esrc = (const int*)d_in[18];
    const int* edst = (const int*)d_in[19];
    const int* erel = (const int*)d_in[20];
    float* out = (float*)d_out;

    float *p_hsnorm, *p_q, *p_k, *p_v, *p_o, *p_t1, *p_out, *p_h1, *p_f, *p_score;
    cudaGetSymbolAddress((void**)&p_hsnorm, g_hsnorm);
    cudaGetSymbolAddress((void**)&p_q, g_q);
    cudaGetSymbolAddress((void**)&p_k, g_k);
    cudaGetSymbolAddress((void**)&p_v, g_v);
    cudaGetSymbolAddress((void**)&p_o, g_o);
    cudaGetSymbolAddress((void**)&p_t1, g_t1);
    cudaGetSymbolAddress((void**)&p_out, g_out);
    cudaGetSymbolAddress((void**)&p_h1, g_h1);
    cudaGetSymbolAddress((void**)&p_f, g_f);
    cudaGetSymbolAddress((void**)&p_score, g_score);

    // 1. ln0
    ln_kernel<<<M_, 256>>>(hidden, ln0g, ln0b, p_hsnorm);

    // 2. Q, K, V GEMMs  (M=4096, N=1024, K=1024)
    dim3 gD(D_ / 128, M_ / 128);
    mma_gemm_kernel<false, true,  false><<<gD, 256>>>(p_hsnorm, Wq, bq, nullptr, p_q, M_, D_, D_);
    mma_gemm_kernel<false, false, false><<<gD, 256>>>(p_hsnorm, Wk, nullptr, nullptr, p_k, M_, D_, D_);
    mma_gemm_kernel<false, false, false><<<gD, 256>>>(p_hsnorm, Wv, nullptr, nullptr, p_v, M_, D_, D_);

    // 3. edge scores
    score_kernel<<<(B_ * E_) / 4, dim3(32, 4)>>>(p_q, p_k, rel_tab, esrc, edst, erel, p_score);

    // 4. deterministic binning by dst
    zero_cnt_kernel<<<(B_ * L_) / 256, 256>>>();
    hist_kernel<<<(B_ * E_) / 256, 256>>>(edst);
    scan_kernel<<<B_, L_>>>();
    fill_kernel<<<128, 32>>>(edst);

    // 5. aggregation -> g_o
    agg_kernel<<<dim3(L_, B_), 256>>>(p_v, rel_tab, esrc, erel, p_score);

    // 6. t1 = hs_norm + o @ Wo + bo ; ln1 -> out
    mma_gemm_kernel<false, true, true><<<gD, 256>>>(p_o, Wo, bo, p_hsnorm, p_t1, M_, D_, D_);
    ln_kernel<<<M_, 256>>>(p_t1, ln1g, ln1b, p_out);

    // 7. FFN: h1 = relu(out @ W1 + b1); f = out + h1 @ W2 + b2
    dim3 gDF(DF_ / 128, M_ / 128);
    mma_gemm_kernel<true, true, false><<<gDF, 256>>>(p_out, W1, b1, nullptr, p_h1, M_, DF_, D_);
    mma_gemm_kernel<false, true, true><<<gD, 256>>>(p_h1, W2, b2, p_out, p_f, M_, D_, DF_);

    // 8. graph_rep = ln2(f); out = hidden + elu(graph_rep)
    ln_elu_res_kernel<<<M_, 256>>>(p_f, ln2g, ln2b, hidden, out);
}

// round 3
// speedup vs baseline: 2.7544x; 1.4157x over previous
#include <cuda_runtime.h>
#include <cuda_bf16.h>
#include <math.h>

// Problem constants
#define B_  4
#define L_  1024
#define D_  1024
#define DF_ 4096
#define E_  32768
#define R_  64
#define M_  (B_ * L_)          // 4096 rows total
#define EPS_ 1e-6f

// ---------------------------------------------------------------------------
// Scratch
// ---------------------------------------------------------------------------
__device__ float g_hsnorm[M_ * D_];
__device__ float g_q[M_ * D_];
__device__ float g_k[M_ * D_];
__device__ float g_v[M_ * D_];
__device__ float g_o[M_ * D_];
__device__ float g_t1[M_ * D_];
__device__ float g_out[M_ * D_];
__device__ float g_h1[M_ * DF_];
__device__ float g_f[M_ * D_];
__device__ float g_score[B_ * E_];
__device__ int   g_perm[B_ * E_];
__device__ int   g_cnt[B_ * L_];
__device__ int   g_off[B_ * (L_ + 1)];

// ---------------------------------------------------------------------------
// LayerNorm helpers
// ---------------------------------------------------------------------------
__device__ __forceinline__ void row_moments(float4 v, float& mean, float& rstd,
                                            float* sh1, float* sh2) {
    float s  = v.x + v.y + v.z + v.w;
    float sq = v.x * v.x + v.y * v.y + v.z * v.z + v.w * v.w;
    #pragma unroll
    for (int o = 16; o; o >>= 1) {
        s  += __shfl_xor_sync(0xffffffffu, s, o);
        sq += __shfl_xor_sync(0xffffffffu, sq, o);
    }
    int warp = threadIdx.x >> 5, lane = threadIdx.x & 31;
    if (lane == 0) { sh1[warp] = s; sh2[warp] = sq; }
    __syncthreads();
    if (threadIdx.x < 8) {
        s = sh1[threadIdx.x]; sq = sh2[threadIdx.x];
        #pragma unroll
        for (int o = 4; o; o >>= 1) {
            s  += __shfl_xor_sync(0xffu, s, o);
            sq += __shfl_xor_sync(0xffu, sq, o);
        }
        if (threadIdx.x == 0) { sh1[0] = s; sh2[0] = sq; }
    }
    __syncthreads();
    mean = sh1[0] * (1.0f / D_);
    float var = sh2[0] * (1.0f / D_) - mean * mean;
    rstd = rsqrtf(var + EPS_);
}

__global__ void ln_kernel(const float* __restrict__ x, const float* __restrict__ g,
                          const float* __restrict__ b, float* __restrict__ y) {
    __shared__ float sh1[8], sh2[8];
    size_t row = blockIdx.x;
    int t = threadIdx.x;
    float4 v = ((const float4*)(x + row * D_))[t];
    float mean, rstd;
    row_moments(v, mean, rstd, sh1, sh2);
    float4 gv = ((const float4*)g)[t];
    float4 bv = ((const float4*)b)[t];
    float4 o;
    o.x = (v.x - mean) * rstd * gv.x + bv.x;
    o.y = (v.y - mean) * rstd * gv.y + bv.y;
    o.z = (v.z - mean) * rstd * gv.z + bv.z;
    o.w = (v.w - mean) * rstd * gv.w + bv.w;
    ((float4*)(y + row * D_))[t] = o;
}

__global__ void ln_elu_res_kernel(const float* __restrict__ x, const float* __restrict__ g,
                                  const float* __restrict__ b,
                                  const float* __restrict__ hidden,
                                  float* __restrict__ out) {
    __shared__ float sh1[8], sh2[8];
    size_t row = blockIdx.x;
    int t = threadIdx.x;
    float4 v = ((const float4*)(x + row * D_))[t];
    float mean, rstd;
    row_moments(v, mean, rstd, sh1, sh2);
    float4 gv = ((const float4*)g)[t];
    float4 bv = ((const float4*)b)[t];
    float4 hv = ((const float4*)(hidden + row * D_))[t];
    float n0 = (v.x - mean) * rstd * gv.x + bv.x;
    float n1 = (v.y - mean) * rstd * gv.y + bv.y;
    float n2 = (v.z - mean) * rstd * gv.z + bv.z;
    float n3 = (v.w - mean) * rstd * gv.w + bv.w;
    float4 o;
    o.x = hv.x + (n0 > 0.f ? n0 : expm1f(n0));
    o.y = hv.y + (n1 > 0.f ? n1 : expm1f(n1));
    o.z = hv.z + (n2 > 0.f ? n2 : expm1f(n2));
    o.w = hv.w + (n3 > 0.f ? n3 : expm1f(n3));
    ((float4*)(out + row * D_))[t] = o;
}

// ---------------------------------------------------------------------------
// TF32 tensor-core GEMM v3: C[M,N] = A@B (+bias)(+res)(+relu)
// CTA tile 128x256, 8 warps (2x4), warp tile 64x64, BK=16.
// cp.async double-buffered pipeline; raw fp32 bits fed to tf32 mma (truncate).
// A smem row-major pitch 20 (conflict-free frag LDS); B k-major pitch 264.
// ---------------------------------------------------------------------------
__device__ __forceinline__ void mma_tf32(float* c, const unsigned* a, const unsigned* b) {
    asm volatile(
        "mma.sync.aligned.m16n8k8.row.col.f32.tf32.tf32.f32 "
        "{%0,%1,%2,%3}, {%4,%5,%6,%7}, {%8,%9}, {%0,%1,%2,%3};"
        : "+f"(c[0]), "+f"(c[1]), "+f"(c[2]), "+f"(c[3])
        : "r"(a[0]), "r"(a[1]), "r"(a[2]), "r"(a[3]), "r"(b[0]), "r"(b[1]));
}

#define CP16(dst, src) \
    asm volatile("cp.async.cg.shared.global [%0], [%1], 16;\n" :: "r"(dst), "l"(src))

#define AP   20           // A smem pitch (words)
#define BP   264          // B smem pitch (words)
#define ASTG (128 * AP)   // words per A stage = 2560
#define BSTG (16 * BP)    // words per B stage = 4224
#define GEMM_SMEM_BYTES ((2 * ASTG + 2 * BSTG) * 4)   // 54272

template <bool RELU, bool BIAS, bool RES>
__global__ __launch_bounds__(256, 1) void mma_gemm_v3(
    const float* __restrict__ A, const float* __restrict__ Bm,
    const float* __restrict__ bias, const float* __restrict__ res,
    float* __restrict__ C, int M, int N, int K) {
    extern __shared__ unsigned sm[];
    unsigned* As = sm;                 // [2][128][AP]
    unsigned* Bs = sm + 2 * ASTG;      // [2][16][BP]
    int tid = threadIdx.x;
    int warp = tid >> 5, lane = tid & 31;
    int g = lane >> 2, tg = lane & 3;
    int bm = blockIdx.y * 128, bn = blockIdx.x * 256;
    int wm = (warp & 1) * 64, wn = (warp >> 1) * 64;

    // cp.async assignments
    int arow = tid >> 1, ahalf = (tid & 1) * 8;   // A: 2x 16B per thread
    const float* aptr = A + (size_t)(bm + arow) * K + ahalf;
    unsigned a_dst = (unsigned)__cvta_generic_to_shared(As + arow * AP + ahalf);
    int brow = tid >> 4, bcg = (tid & 15) * 16;   // B: 4x 16B per thread
    const float* bptr = Bm + (size_t)brow * N + bn + bcg;
    unsigned b_dst = (unsigned)__cvta_generic_to_shared(Bs + brow * BP + bcg);

    int ntiles = K >> 4;

    // Prologue: stages 0 and 1
    #pragma unroll
    for (int s = 0; s < 2; s++) {
        const float* ap = aptr + s * 16;
        const float* bp = bptr + (size_t)s * 16 * N;
        unsigned ad = a_dst + s * ASTG * 4;
        unsigned bd = b_dst + s * BSTG * 4;
        CP16(ad, ap); CP16(ad + 16, ap + 4);
        CP16(bd, bp); CP16(bd + 16, bp + 4);
        CP16(bd + 32, bp + 8); CP16(bd + 48, bp + 12);
        asm volatile("cp.async.commit_group;\n");
    }

    float acc[4][8][4];
    #pragma unroll
    for (int mt = 0; mt < 4; mt++)
        #pragma unroll
        for (int nt = 0; nt < 8; nt++)
            #pragma unroll
            for (int r = 0; r < 4; r++) acc[mt][nt][r] = 0.f;

    for (int kt = 0; kt < ntiles; kt++) {
        int cur = kt & 1;
        if (kt == ntiles - 1) asm volatile("cp.async.wait_group 0;\n");
        else                  asm volatile("cp.async.wait_group 1;\n");
        __syncthreads();

        const unsigned* Ab = As + cur * ASTG;
        const unsigned* Bb = Bs + cur * BSTG;
        #pragma unroll
        for (int ks = 0; ks < 2; ks++) {
            int k0 = ks * 8;
            unsigned af[4][4], bf[8][2];
            #pragma unroll
            for (int mt = 0; mt < 4; mt++) {
                const unsigned* p = Ab + (wm + mt * 16 + g) * AP + k0 + tg;
                af[mt][0] = p[0];
                af[mt][1] = p[8 * AP];
                af[mt][2] = p[4];
                af[mt][3] = p[8 * AP + 4];
            }
            #pragma unroll
            for (int nt = 0; nt < 8; nt++) {
                const unsigned* p = Bb + (k0 + tg) * BP + wn + nt * 8 + g;
                bf[nt][0] = p[0];
                bf[nt][1] = p[4 * BP];
            }
            #pragma unroll
            for (int mt = 0; mt < 4; mt++)
                #pragma unroll
                for (int nt = 0; nt < 8; nt++)
                    mma_tf32(acc[mt][nt], af[mt], bf[nt]);
        }

        if (kt + 2 < ntiles) {
            __syncthreads();   // all MMA reads of 'cur' done before refill
            int k0 = (kt + 2) * 16;
            const float* ap = aptr + k0;
            const float* bp = bptr + (size_t)k0 * N;
            unsigned ad = a_dst + cur * ASTG * 4;
            unsigned bd = b_dst + cur * BSTG * 4;
            CP16(ad, ap); CP16(ad + 16, ap + 4);
            CP16(bd, bp); CP16(bd + 16, bp + 4);
            CP16(bd + 32, bp + 8); CP16(bd + 48, bp + 12);
            asm volatile("cp.async.commit_group;\n");
        }
    }

    // Epilogue
    #pragma unroll
    for (int mt = 0; mt < 4; mt++) {
        #pragma unroll
        for (int nt = 0; nt < 8; nt++) {
            int col = bn + wn + nt * 8 + tg * 2;
            #pragma unroll
            for (int h = 0; h < 2; h++) {
                int row = bm + wm + mt * 16 + g + h * 8;
                float vx = acc[mt][nt][2 * h];
                float vy = acc[mt][nt][2 * h + 1];
                if (BIAS) {
                    float2 bb = *(const float2*)(bias + col);
                    vx += bb.x; vy += bb.y;
                }
                if (RES) {
                    float2 rr = *(const float2*)(res + (size_t)row * N + col);
                    vx += rr.x; vy += rr.y;
                }
                if (RELU) { vx = fmaxf(vx, 0.f); vy = fmaxf(vy, 0.f); }
                *(float2*)(C + (size_t)row * N + col) = make_float2(vx, vy);
            }
        }
    }
}

// ---------------------------------------------------------------------------
// Edge scores
// ---------------------------------------------------------------------------
__global__ void score_kernel(const float* __restrict__ Q, const float* __restrict__ Km,
                             const float* __restrict__ rel_table,
                             const int* __restrict__ src, const int* __restrict__ dst,
                             const int* __restrict__ rel, float* __restrict__ score) {
    int idx = blockIdx.x * 4 + threadIdx.y;
    int b = idx >> 15;
    int lane = threadIdx.x;
    int s = src[idx], d = dst[idx], r = rel[idx];
    const float4* kr = (const float4*)(Km + ((size_t)b * L_ + s) * D_);
    const float4* qr = (const float4*)(Q + ((size_t)b * L_ + d) * D_);
    const float4* er = (const float4*)(rel_table + (size_t)r * D_);
    float acc = 0.f;
    #pragma unroll
    for (int i = 0; i < 8; i++) {
        int c = lane + 32 * i;
        float4 kv = kr[c], qv = qr[c], ev = er[c];
        acc = fmaf(kv.x + ev.x, qv.x, acc);
        acc = fmaf(kv.y + ev.y, qv.y, acc);
        acc = fmaf(kv.z + ev.z, qv.z, acc);
        acc = fmaf(kv.w + ev.w, qv.w, acc);
    }
    #pragma unroll
    for (int o = 16; o; o >>= 1) acc += __shfl_xor_sync(0xffffffffu, acc, o);
    if (lane == 0) {
        float sc = acc * 0.03125f;
        sc = fminf(fmaxf(sc, -10.f), 10.f);
        score[idx] = expf(sc);
    }
}

// ---------------------------------------------------------------------------
// Deterministic binning
// ---------------------------------------------------------------------------
__global__ void zero_cnt_kernel() {
    int i = blockIdx.x * 256 + threadIdx.x;
    if (i < B_ * L_) g_cnt[i] = 0;
}

__global__ void hist_kernel(const int* __restrict__ edge_dst) {
    int idx = blockIdx.x * 256 + threadIdx.x;
    if (idx < B_ * E_) atomicAdd(&g_cnt[(idx >> 15) * L_ + edge_dst[idx]], 1);
}

__global__ void scan_kernel() {
    int b = blockIdx.x, t = threadIdx.x;
    __shared__ int s[L_];
    int c = g_cnt[b * L_ + t];
    s[t] = c;
    __syncthreads();
    for (int off = 1; off < L_; off <<= 1) {
        int v = (t >= off) ? s[t - off] : 0;
        __syncthreads();
        s[t] += v;
        __syncthreads();
    }
    g_off[b * (L_ + 1) + t] = s[t] - c;
    if (t == L_ - 1) g_off[b * (L_ + 1) + L_] = s[t];
}

// Block-cooperative stable fill: 8 warps per block share SMEM-staged edge
// chunks; each warp owns one (b, node). Ballot/popc preserves edge-id order
// within each bin -> deterministic accumulation order downstream.
__global__ void fill_block_kernel(const int* __restrict__ edge_dst) {
    __shared__ int sd[1024];
    int b = blockIdx.x >> 7;                 // 512 blocks: 128 per batch
    int nodebase = (blockIdx.x & 127) * 8;
    int warp = threadIdx.x >> 5, lane = threadIdx.x & 31;
    int node = nodebase + warp;
    int w = g_off[b * (L_ + 1) + node];
    int* pb = g_perm + b * E_;
    const int* dv = edge_dst + b * E_;
    for (int base = 0; base < E_; base += 1024) {
        __syncthreads();
        #pragma unroll
        for (int i = 0; i < 4; i++) sd[threadIdx.x + 256 * i] = dv[base + threadIdx.x + 256 * i];
        __syncthreads();
        for (int c = 0; c < 1024; c += 32) {
            int d = sd[c + lane];
            unsigned m = __ballot_sync(0xffffffffu, d == node);
            if (d == node) pb[w + __popc(m & ((1u << lane) - 1))] = base + c + lane;
            w += __popc(m);
        }
    }
}

// ---------------------------------------------------------------------------
// Aggregation
// ---------------------------------------------------------------------------
__global__ void agg_kernel(const float* __restrict__ V, const float* __restrict__ rel_table,
                           const int* __restrict__ src, const int* __restrict__ rel,
                           const float* __restrict__ score) {
    int node = blockIdx.x, b = blockIdx.y;
    int t = threadIdx.x;
    int beg = g_off[b * (L_ + 1) + node];
    int end = g_off[b * (L_ + 1) + node + 1];
    const int* pb = g_perm + b * E_;
    float4 acc = make_float4(0.f, 0.f, 0.f, 0.f);
    float z = 0.f;
    for (int i = beg; i < end; i++) {
        int e = pb[i];
        float s = score[b * E_ + e];
        int sn = src[b * E_ + e];
        int r = rel[b * E_ + e];
        float4 vv = *(const float4*)(V + ((size_t)b * L_ + sn) * D_ + 4 * t);
        float4 ev = *(const float4*)(rel_table + (size_t)r * D_ + 4 * t);
        acc.x = fmaf(s, vv.x + ev.x, acc.x);
        acc.y = fmaf(s, vv.y + ev.y, acc.y);
        acc.z = fmaf(s, vv.z + ev.z, acc.z);
        acc.w = fmaf(s, vv.w + ev.w, acc.w);
        z += s;
    }
    float inv = 1.0f / z;
    float4 o = make_float4(acc.x * inv, acc.y * inv, acc.z * inv, acc.w * inv);
    *(float4*)(g_o + ((size_t)b * L_ + node) * D_ + 4 * t) = o;
}

// ---------------------------------------------------------------------------
// Launch
// ---------------------------------------------------------------------------
extern "C" void kernel_launch(void* const* d_in, const int* in_sizes, int n_in,
                              void* d_out, int out_size) {
    const float* hidden  = (const float*)d_in[0];
    const float* rel_tab = (const float*)d_in[1];
    const float* Wq = (const float*)d_in[2];
    const float* bq = (const float*)d_in[3];
    const float* Wk = (const float*)d_in[4];
    const float* Wv = (const float*)d_in[5];
    const float* Wo = (const float*)d_in[6];
    const float* bo = (const float*)d_in[7];
    const float* ln0g = (const float*)d_in[8];
    const float* ln0b = (const float*)d_in[9];
    const float* ln1g = (const float*)d_in[10];
    const float* ln1b = (const float*)d_in[11];
    const float* W1 = (const float*)d_in[12];
    const float* b1 = (const float*)d_in[13];
    const float* W2 = (const float*)d_in[14];
    const float* b2 = (const float*)d_in[15];
    const float* ln2g = (const float*)d_in[16];
    const float* ln2b = (const float*)d_in[17];
    const int* esrc = (const int*)d_in[18];
    const int* edst = (const int*)d_in[19];
    const int* erel = (const int*)d_in[20];
    float* out = (float*)d_out;

    float *p_hsnorm, *p_q, *p_k, *p_v, *p_o, *p_t1, *p_out, *p_h1, *p_f, *p_score;
    cudaGetSymbolAddress((void**)&p_hsnorm, g_hsnorm);
    cudaGetSymbolAddress((void**)&p_q, g_q);
    cudaGetSymbolAddress((void**)&p_k, g_k);
    cudaGetSymbolAddress((void**)&p_v, g_v);
    cudaGetSymbolAddress((void**)&p_o, g_o);
    cudaGetSymbolAddress((void**)&p_t1, g_t1);
    cudaGetSymbolAddress((void**)&p_out, g_out);
    cudaGetSymbolAddress((void**)&p_h1, g_h1);
    cudaGetSymbolAddress((void**)&p_f, g_f);
    cudaGetSymbolAddress((void**)&p_score, g_score);

    // Opt-in to >48KB dynamic smem (idempotent host-side attribute set)
    cudaFuncSetAttribute((const void*)mma_gemm_v3<false, true,  false>,
                         cudaFuncAttributeMaxDynamicSharedMemorySize, GEMM_SMEM_BYTES);
    cudaFuncSetAttribute((const void*)mma_gemm_v3<false, false, false>,
                         cudaFuncAttributeMaxDynamicSharedMemorySize, GEMM_SMEM_BYTES);
    cudaFuncSetAttribute((const void*)mma_gemm_v3<false, true,  true>,
                         cudaFuncAttributeMaxDynamicSharedMemorySize, GEMM_SMEM_BYTES);
    cudaFuncSetAttribute((const void*)mma_gemm_v3<true,  true,  false>,
                         cudaFuncAttributeMaxDynamicSharedMemorySize, GEMM_SMEM_BYTES);

    // 1. ln0
    ln_kernel<<<M_, 256>>>(hidden, ln0g, ln0b, p_hsnorm);

    // 2. Q, K, V GEMMs (M=4096, N=1024, K=1024); CTA tile 128x256
    dim3 gD(D_ / 256, M_ / 128);
    mma_gemm_v3<false, true,  false><<<gD, 256, GEMM_SMEM_BYTES>>>(p_hsnorm, Wq, bq, nullptr, p_q, M_, D_, D_);
    mma_gemm_v3<false, false, false><<<gD, 256, GEMM_SMEM_BYTES>>>(p_hsnorm, Wk, nullptr, nullptr, p_k, M_, D_, D_);
    mma_gemm_v3<false, false, false><<<gD, 256, GEMM_SMEM_BYTES>>>(p_hsnorm, Wv, nullptr, nullptr, p_v, M_, D_, D_);

    // 3. edge scores
    score_kernel<<<(B_ * E_) / 4, dim3(32, 4)>>>(p_q, p_k, rel_tab, esrc, edst, erel, p_score);

    // 4. deterministic binning by dst
    zero_cnt_kernel<<<(B_ * L_) / 256, 256>>>();
    hist_kernel<<<(B_ * E_) / 256, 256>>>(edst);
    scan_kernel<<<B_, L_>>>();
    fill_block_kernel<<<512, 256>>>(edst);

    // 5. aggregation -> g_o
    agg_kernel<<<dim3(L_, B_), 256>>>(p_v, rel_tab, esrc, erel, p_score);

    // 6. t1 = hs_norm + o @ Wo + bo ; ln1 -> out
    mma_gemm_v3<false, true, true><<<gD, 256, GEMM_SMEM_BYTES>>>(p_o, Wo, bo, p_hsnorm, p_t1, M_, D_, D_);
    ln_kernel<<<M_, 256>>>(p_t1, ln1g, ln1b, p_out);

    // 7. FFN
    dim3 gDF(DF_ / 256, M_ / 128);
    mma_gemm_v3<true,  true, false><<<gDF, 256, GEMM_SMEM_BYTES>>>(p_out, W1, b1, nullptr, p_h1, M_, DF_, D_);
    mma_gemm_v3<false, true, true ><<<gD,  256, GEMM_SMEM_BYTES>>>(p_h1, W2, b2, p_out, p_f, M_, D_, DF_);

    // 8. final
    ln_elu_res_kernel<<<M_, 256>>>(p_f, ln2g, ln2b, hidden, out);
}